// round 10
// baseline (speedup 1.0000x reference)
#include <cuda_runtime.h>
#include <cuda_bf16.h>
#include <cstdint>

namespace {
constexpr int Bb = 8, S = 4096, E = 1024, H = 8, D = 128, NW = 32;
constexpr float SCALE = 0.08838834764831845f;  // D^-0.5
}

// intermediates (device globals; no runtime alloc). q,k: hi only (single-pass QK).
__device__ __align__(128) __nv_bfloat16 g_qh[(size_t)Bb*H*S*D];
__device__ __align__(128) __nv_bfloat16 g_kh[(size_t)Bb*H*S*D];
__device__ __align__(128) __nv_bfloat16 g_vh[(size_t)Bb*H*S*D], g_vl[(size_t)Bb*H*S*D];
__device__ __align__(128) __nv_bfloat16 g_ah[(size_t)Bb*S*E],   g_al[(size_t)Bb*S*E];
__device__ __align__(128) __nv_bfloat16 g_woh[(size_t)E*E],     g_wol[(size_t)E*E];

// ---------------- low-level helpers ----------------
__device__ __forceinline__ uint32_t smem_u32(const void* p) {
    uint32_t a;
    asm("{ .reg .u64 t; cvta.to.shared.u64 t, %1; cvt.u32.u64 %0, t; }" : "=r"(a) : "l"(p));
    return a;
}
template<int RB>
__device__ __forceinline__ uint32_t toff(int r, int cb) {
    return (uint32_t)(r * RB + ((((cb >> 4) ^ (r & 7)) & (RB / 16 - 1)) << 4) + (cb & 15));
}
__device__ __forceinline__ void ldm_x4(uint32_t* a, uint32_t addr) {
    asm volatile("ldmatrix.sync.aligned.m8n8.x4.shared.b16 {%0,%1,%2,%3}, [%4];"
        : "=r"(a[0]), "=r"(a[1]), "=r"(a[2]), "=r"(a[3]) : "r"(addr));
}
__device__ __forceinline__ void ldm_x4t(uint32_t* a, uint32_t addr) {
    asm volatile("ldmatrix.sync.aligned.m8n8.x4.trans.shared.b16 {%0,%1,%2,%3}, [%4];"
        : "=r"(a[0]), "=r"(a[1]), "=r"(a[2]), "=r"(a[3]) : "r"(addr));
}
__device__ __forceinline__ void mma16816(float* c, const uint32_t* a, const uint32_t* b) {
    asm volatile("mma.sync.aligned.m16n8k16.row.col.f32.bf16.bf16.f32 "
        "{%0,%1,%2,%3},{%4,%5,%6,%7},{%8,%9},{%0,%1,%2,%3};"
        : "+f"(c[0]), "+f"(c[1]), "+f"(c[2]), "+f"(c[3])
        : "r"(a[0]), "r"(a[1]), "r"(a[2]), "r"(a[3]), "r"(b[0]), "r"(b[1]));
}
__device__ __forceinline__ void cpa16(uint32_t dst, const void* src) {
    asm volatile("cp.async.cg.shared.global [%0], [%1], 16;" :: "r"(dst), "l"(src));
}
#define CPA_COMMIT() asm volatile("cp.async.commit_group;" ::: "memory")
template<int N>
__device__ __forceinline__ void cpa_wait() {
    asm volatile("cp.async.wait_group %0;" :: "n"(N) : "memory");
}

// NN gemm, B loaded via x4 (two n-tiles per ldmatrix).
// x4 lane mapping (groups of 8 lanes -> matrices m0..m3):
//   m0=(n..n+7, k+0..7), m1=(n..n+7, k+8..15), m2=(n+8..15, k+0..7), m3=(n+8..15, k+8..15)
template<int NK, int ARB, int BRB>
__device__ __forceinline__ void gemm_nn(uint32_t aB, int acb, uint32_t bB, int bcb,
                                        float acc[2][8][4], int lane, int m0, int n0) {
#pragma unroll
    for (int ks = 0; ks < NK; ks++) {
        uint32_t a[2][4];
#pragma unroll
        for (int mt = 0; mt < 2; mt++)
            ldm_x4(a[mt], aB + toff<ARB>(m0 + mt * 16 + (lane & 15),
                                         acb + ks * 32 + ((lane >> 4) << 4)));
#pragma unroll
        for (int np = 0; np < 4; np++) {
            uint32_t b4[4];
            ldm_x4(b4, bB + toff<BRB>(n0 + np * 16 + ((lane >> 4) << 3) + (lane & 7),
                                      bcb + ks * 32 + (((lane >> 3) & 1) << 4)));
            mma16816(acc[0][np * 2],     a[0], b4);
            mma16816(acc[1][np * 2],     a[1], b4);
            mma16816(acc[0][np * 2 + 1], a[0], b4 + 2);
            mma16816(acc[1][np * 2 + 1], a[1], b4 + 2);
        }
    }
}
// NT gemm: B stored [k rows][n cols]; x4.trans loads two n-tiles:
//   m0=(k+0..7, n..n+7), m1=(k+8..15, n..n+7), m2=(k+0..7, n+8..15), m3=(k+8..15, n+8..15)
template<int NK, int ARB, int BRB>
__device__ __forceinline__ void gemm_nt(uint32_t aB, int acb, uint32_t bB,
                                        float acc[2][8][4], int lane, int m0, int n0) {
#pragma unroll
    for (int ks = 0; ks < NK; ks++) {
        uint32_t a[2][4];
#pragma unroll
        for (int mt = 0; mt < 2; mt++)
            ldm_x4(a[mt], aB + toff<ARB>(m0 + mt * 16 + (lane & 15),
                                         acb + ks * 32 + ((lane >> 4) << 4)));
#pragma unroll
        for (int np = 0; np < 4; np++) {
            uint32_t b4[4];
            ldm_x4t(b4, bB + toff<BRB>(ks * 16 + (((lane >> 3) & 1) << 3) + (lane & 7),
                                       (n0 + np * 16 + ((lane >> 4) << 3)) * 2));
            mma16816(acc[0][np * 2],     a[0], b4);
            mma16816(acc[1][np * 2],     a[1], b4);
            mma16816(acc[0][np * 2 + 1], a[0], b4 + 2);
            mma16816(acc[1][np * 2 + 1], a[1], b4 + 2);
        }
    }
}
__device__ __forceinline__ void split2(float a, float b, uint32_t& hi, uint32_t& lo) {
    __nv_bfloat16 ha = __float2bfloat16(a), hb = __float2bfloat16(b);
    __nv_bfloat16 la = __float2bfloat16(a - __bfloat162float(ha));
    __nv_bfloat16 lb = __float2bfloat16(b - __bfloat162float(hb));
    hi = ((uint32_t)__bfloat16_as_ushort(hb) << 16) | __bfloat16_as_ushort(ha);
    lo = ((uint32_t)__bfloat16_as_ushort(lb) << 16) | __bfloat16_as_ushort(la);
}
__device__ __forceinline__ uint32_t pack2h(float a, float b) {
    return ((uint32_t)__bfloat16_as_ushort(__float2bfloat16(b)) << 16) |
           __bfloat16_as_ushort(__float2bfloat16(a));
}
__device__ __forceinline__ float fast_exp(float x) {
    float y = x * 1.4426950408889634f;
    float z = y + 12582912.0f;
    int   n = __float_as_int(z) - 0x4B400000;
    float f = y - (z - 12582912.0f);
    float p = fmaf(f, 1.5403530e-4f, 1.3333558e-3f);
    p = fmaf(f, p, 9.6181291e-3f);
    p = fmaf(f, p, 5.5504109e-2f);
    p = fmaf(f, p, 2.4022651e-1f);
    p = fmaf(f, p, 6.9314718e-1f);
    p = fmaf(f, p, 1.0f);
    return __int_as_float(__float_as_int(p) + (n << 23));
}
// stage loaders (cp.async)
__device__ __forceinline__ void stage128(uint32_t dst, const __nv_bfloat16* g, int ld, int t) {
#pragma unroll
    for (int it = 0; it < 8; it++) {
        int idx = t + it * 256, r = idx >> 4, c8 = idx & 15;
        cpa16(dst + toff<256>(r, c8 * 16), g + (size_t)r * ld + c8 * 8);
    }
}
__device__ __forceinline__ void stage64x128(uint32_t dst, const __nv_bfloat16* g, int ld, int t) {
#pragma unroll
    for (int it = 0; it < 4; it++) {
        int idx = t + it * 256, r = idx >> 4, c8 = idx & 15;
        cpa16(dst + toff<256>(r, c8 * 16), g + (size_t)r * ld + c8 * 8);
    }
}
__device__ __forceinline__ void cvt64(const float* __restrict__ g, int ld,
                                      char* sh, char* sl, int t) {
#pragma unroll
    for (int it = 0; it < 4; it++) {
        int idx = t + it * 256, r = idx >> 3, c8 = idx & 7;
        const float* p = g + (size_t)r * ld + c8 * 8;
        float x[8];
        *(float4*)x = *(const float4*)p;
        *(float4*)(x + 4) = *(const float4*)(p + 4);
        uint32_t h[4], l[4];
#pragma unroll
        for (int j = 0; j < 4; j++) split2(x[j * 2], x[j * 2 + 1], h[j], l[j]);
        uint32_t o = toff<128>(r, c8 * 16);
        *(uint4*)(sh + o) = *(uint4*)h;
        *(uint4*)(sl + o) = *(uint4*)l;
    }
}

// ---------------- prep: Wo fp32 -> hi/lo bf16 rows ----------------
__global__ void __launch_bounds__(256) prep_wo_kernel(const float* __restrict__ Wo) {
    int idx = blockIdx.x * 256 + threadIdx.x;
    int r = idx >> 7, c8 = idx & 127;
    const float* p = Wo + (size_t)r * E + c8 * 8;
    float x[8];
    *(float4*)x = *(const float4*)p;
    *(float4*)(x + 4) = *(const float4*)(p + 4);
    uint32_t h[4], l[4];
#pragma unroll
    for (int j = 0; j < 4; j++) split2(x[j * 2], x[j * 2 + 1], h[j], l[j]);
    *(uint4*)(g_woh + (size_t)r * E + c8 * 8) = *(uint4*)h;
    *(uint4*)(g_wol + (size_t)r * E + c8 * 8) = *(uint4*)l;
}

// ---------------- proj (merged q/k/v), 3-term; q/k store hi only ----------------
__global__ void __launch_bounds__(256, 2)
proj_kernel(const float* __restrict__ xq, const float* __restrict__ xk, const float* __restrict__ xv,
            const float* __restrict__ Wq, const float* __restrict__ Wk, const float* __restrict__ Wv) {
    extern __shared__ char sm[];
    uint32_t sb = smem_u32(sm);
    const int t = threadIdx.x, lane = t & 31, wid = t >> 5;
    const int w = blockIdx.x, h = blockIdx.y, z = blockIdx.z;
    const int tz = z / Bb, b = z % Bb;
    const float* x  = (tz == 0) ? xq : (tz == 1) ? xk : xv;
    const float* Wt = (tz == 0) ? Wq : (tz == 1) ? Wk : Wv;
    __nv_bfloat16* oh = (tz == 0) ? g_qh : (tz == 1) ? g_kh : g_vh;
    const float scale = (tz == 0) ? SCALE : 1.0f;

    const int m0 = (wid & 3) * 32, n0 = (wid >> 2) * 64;
    float acc[2][8][4] = {};

    const float* xb = x + ((size_t)(b * S + w * 128)) * E + h * D;
    for (int dc = 0; dc < 2; dc++) {
        __syncthreads();
        cvt64(xb + dc * 64, E, sm, sm + 16384, t);
        cvt64(Wt + dc * 64, D, sm + 32768, sm + 49152, t);
        __syncthreads();
        gemm_nn<4, 128, 128>(sb,         0, sb + 32768, 0, acc, lane, m0, n0);
        gemm_nn<4, 128, 128>(sb,         0, sb + 49152, 0, acc, lane, m0, n0);
        gemm_nn<4, 128, 128>(sb + 16384, 0, sb + 32768, 0, acc, lane, m0, n0);
    }

    size_t base = ((size_t)(b * H + h) * S + w * 128);
#pragma unroll
    for (int mt = 0; mt < 2; mt++)
#pragma unroll
        for (int hf = 0; hf < 2; hf++) {
            int r = m0 + mt * 16 + (lane >> 2) + hf * 8;
            size_t row = (base + r) * D;
#pragma unroll
            for (int nt = 0; nt < 8; nt++) {
                int c = n0 + nt * 8 + (lane & 3) * 2;
                float v0 = acc[mt][nt][hf * 2] * scale, v1 = acc[mt][nt][hf * 2 + 1] * scale;
                if (tz < 2) {
                    *(uint32_t*)(oh + row + c) = pack2h(v0, v1);
                } else {
                    uint32_t hi, lo;
                    split2(v0, v1, hi, lo);
                    *(uint32_t*)(g_vh + row + c) = hi;
                    *(uint32_t*)(g_vl + row + c) = lo;
                }
            }
        }
}

// ---------------- attention: single-pass QK, 3-term PV, 3 stages/window ----------------
// smem: Qh 0 | Ph 32K | Pl 64K | buf0 96K | buf1 128K | Lacc 160K
__global__ void __launch_bounds__(256)
attn_kernel() {
    extern __shared__ char sm[];
    uint32_t sb = smem_u32(sm);
    float* Lacc = (float*)(sm + 163840);
    const int t = threadIdx.x, lane = t & 31, wid = t >> 5;
    const int w = blockIdx.x, h = blockIdx.y, b = blockIdx.z;
    const size_t base = (size_t)((b * H + h) * S);
    const int m0 = (wid & 3) * 32, n0 = (wid >> 2) * 64;

    const int j0 = (w > 0) ? w - 1 : 0;
    const int j1 = (w < NW - 1) ? w + 1 : NW - 1;
    const int nstep = (j1 - j0 + 1) * 3;
    const uint32_t bufs[2] = { sb + 98304, sb + 131072 };

    auto issue_stage = [&](int ts) {
        if (ts >= nstep) return;
        int j = j0 + ts / 3, kind = ts % 3;
        uint32_t bf = bufs[ts & 1];
        size_t roff = (base + (size_t)j * 128) * D;
        if (kind == 0) {
            stage128(bf, g_kh + roff, D, t);
        } else {
            size_t so = roff + (size_t)(kind - 1) * 64 * D;
            stage64x128(bf,         g_vh + so, D, t);
            stage64x128(bf + 16384, g_vl + so, D, t);
        }
    };

    if (t < 128) Lacc[t] = 0.0f;
    stage128(sb, g_qh + (base + (size_t)w * 128) * D, D, t);
    issue_stage(0);
    CPA_COMMIT();

    float oacc[2][8][4] = {};

    for (int ts = 0; ts < nstep; ts++) {
        cpa_wait<0>();
        __syncthreads();
        issue_stage(ts + 1);
        CPA_COMMIT();
        const uint32_t bf = bufs[ts & 1];
        const int kind = ts % 3;
        if (kind == 0) {
            float sacc[2][8][4] = {};
            gemm_nn<8, 256, 256>(sb, 0, bf, 0, sacc, lane, m0, n0);   // S = q·k^T (hi only)
#pragma unroll
            for (int mt = 0; mt < 2; mt++)
#pragma unroll
                for (int hf = 0; hf < 2; hf++) {
                    int r = m0 + mt * 16 + (lane >> 2) + hf * 8;
                    float rsum = 0.0f;
#pragma unroll
                    for (int nt = 0; nt < 8; nt++) {
                        float e0 = fast_exp(sacc[mt][nt][hf * 2]);
                        float e1 = fast_exp(sacc[mt][nt][hf * 2 + 1]);
                        rsum += e0 + e1;
                        uint32_t hi, lo;
                        split2(e0, e1, hi, lo);
                        int c = n0 + nt * 8 + (lane & 3) * 2;
                        uint32_t o = toff<256>(r, c * 2);
                        *(uint32_t*)(sm + 32768 + o) = hi;
                        *(uint32_t*)(sm + 65536 + o) = lo;
                    }
                    rsum += __shfl_xor_sync(0xffffffffu, rsum, 1);
                    rsum += __shfl_xor_sync(0xffffffffu, rsum, 2);
                    if ((lane & 3) == 0) atomicAdd(&Lacc[r], rsum);
                }
        } else {
            const int sc = kind - 1;
            gemm_nt<4, 256, 256>(sb + 32768, sc * 128, bf,         oacc, lane, m0, n0);
            gemm_nt<4, 256, 256>(sb + 32768, sc * 128, bf + 16384, oacc, lane, m0, n0);
            gemm_nt<4, 256, 256>(sb + 65536, sc * 128, bf,         oacc, lane, m0, n0);
        }
    }
    __syncthreads();

#pragma unroll
    for (int mt = 0; mt < 2; mt++)
#pragma unroll
        for (int hf = 0; hf < 2; hf++) {
            int r = m0 + mt * 16 + (lane >> 2) + hf * 8;
            float inv = 1.0f / Lacc[r];
            size_t row = ((size_t)b * S + w * 128 + r) * E + h * D;
#pragma unroll
            for (int nt = 0; nt < 8; nt++) {
                int c = n0 + nt * 8 + (lane & 3) * 2;
                uint32_t hi, lo;
                split2(oacc[mt][nt][hf * 2] * inv, oacc[mt][nt][hf * 2 + 1] * inv, hi, lo);
                *(uint32_t*)(g_ah + row + c) = hi;
                *(uint32_t*)(g_al + row + c) = lo;
            }
        }
}

// ---------------- fc: y = att @ Wo^T + bo, K=32 ping-pong ----------------
__global__ void __launch_bounds__(256, 2)
fc_kernel(const float* __restrict__ bo, float* __restrict__ y) {
    extern __shared__ char sm[];
    uint32_t sb = smem_u32(sm);
    const int t = threadIdx.x, lane = t & 31, wid = t >> 5;
    const int nb = blockIdx.x, mb = blockIdx.y;
    const int m0 = (wid & 3) * 32, n0 = (wid >> 2) * 64;

    auto issue_stage = [&](int s) {
        if (s >= 32) return;
        int half = (s & 1) * 64;
#pragma unroll
        for (int it = 0; it < 2; it++) {
            int idx = t + it * 256, r = idx >> 2, c2 = idx & 3;
            uint32_t o = toff<128>(r, half + c2 * 16);
            size_t asrc = (size_t)(mb * 128 + r) * E + s * 32 + c2 * 8;
            size_t wsrc = (size_t)(nb * 128 + r) * E + s * 32 + c2 * 8;
            cpa16(sb         + o, g_ah  + asrc);
            cpa16(sb + 16384 + o, g_al  + asrc);
            cpa16(sb + 32768 + o, g_woh + wsrc);
            cpa16(sb + 49152 + o, g_wol + wsrc);
        }
    };

    issue_stage(0);
    CPA_COMMIT();

    float acc[2][8][4] = {};
    for (int s = 0; s < 32; s++) {
        cpa_wait<0>();
        __syncthreads();
        issue_stage(s + 1);
        CPA_COMMIT();
        const int cb = (s & 1) * 64;
        gemm_nn<2, 128, 128>(sb,         cb, sb + 32768, cb, acc, lane, m0, n0);
        gemm_nn<2, 128, 128>(sb,         cb, sb + 49152, cb, acc, lane, m0, n0);
        gemm_nn<2, 128, 128>(sb + 16384, cb, sb + 32768, cb, acc, lane, m0, n0);
    }

#pragma unroll
    for (int mt = 0; mt < 2; mt++)
#pragma unroll
        for (int hf = 0; hf < 2; hf++) {
            int r = m0 + mt * 16 + (lane >> 2) + hf * 8;
            size_t row = ((size_t)(mb * 128 + r)) * E + nb * 128;
#pragma unroll
            for (int nt = 0; nt < 8; nt++) {
                int c = n0 + nt * 8 + (lane & 3) * 2;
                float2 o;
                o.x = acc[mt][nt][hf * 2]     + bo[nb * 128 + c];
                o.y = acc[mt][nt][hf * 2 + 1] + bo[nb * 128 + c + 1];
                *(float2*)(y + row + c) = o;
            }
        }
}

// ---------------- launcher ----------------
extern "C" void kernel_launch(void* const* d_in, const int* in_sizes, int n_in,
                              void* d_out, int out_size) {
    const float* values = (const float*)d_in[0];
    const float* keys   = (const float*)d_in[1];
    const float* query  = (const float*)d_in[2];
    const float* Wv     = (const float*)d_in[3];
    const float* Wk     = (const float*)d_in[4];
    const float* Wq     = (const float*)d_in[5];
    const float* Wo     = (const float*)d_in[6];
    const float* bo     = (const float*)d_in[7];
    float* out = (float*)d_out;

    const int proj_smem = 65536;
    const int attn_smem = 163840 + 512;
    const int fc_smem   = 65536;
    cudaFuncSetAttribute(proj_kernel, cudaFuncAttributeMaxDynamicSharedMemorySize, proj_smem);
    cudaFuncSetAttribute(attn_kernel, cudaFuncAttributeMaxDynamicSharedMemorySize, attn_smem);
    cudaFuncSetAttribute(fc_kernel,   cudaFuncAttributeMaxDynamicSharedMemorySize, fc_smem);

    prep_wo_kernel<<<512, 256>>>(Wo);

    proj_kernel<<<dim3(NW, H, 3 * Bb), 256, proj_smem>>>(query, keys, values, Wq, Wk, Wv);

    attn_kernel<<<dim3(NW, H, Bb), 256, attn_smem>>>();

    fc_kernel<<<dim3(E / 128, (Bb * S) / 128), 256, fc_smem>>>(bo, out);
}

// round 11
// speedup vs baseline: 2.1685x; 2.1685x over previous
#include <cuda_runtime.h>
#include <cuda_fp16.h>
#include <cstdint>

namespace {
constexpr int Bb = 8, S = 4096, E = 1024, H = 8, D = 128, NW = 32;
constexpr float SCALE = 0.08838834764831845f;  // D^-0.5
}

// intermediates: fp16 single-precision-split-free (device globals; no runtime alloc)
__device__ __align__(128) __half g_q[(size_t)Bb*H*S*D];
__device__ __align__(128) __half g_k[(size_t)Bb*H*S*D];
__device__ __align__(128) __half g_v[(size_t)Bb*H*S*D];
__device__ __align__(128) __half g_a[(size_t)Bb*S*E];
__device__ __align__(128) __half g_wo[(size_t)E*E];

// ---------------- low-level helpers ----------------
__device__ __forceinline__ uint32_t smem_u32(const void* p) {
    uint32_t a;
    asm("{ .reg .u64 t; cvta.to.shared.u64 t, %1; cvt.u32.u64 %0, t; }" : "=r"(a) : "l"(p));
    return a;
}
template<int RB>
__device__ __forceinline__ uint32_t toff(int r, int cb) {
    return (uint32_t)(r * RB + ((((cb >> 4) ^ (r & 7)) & (RB / 16 - 1)) << 4) + (cb & 15));
}
__device__ __forceinline__ void ldm_x4(uint32_t* a, uint32_t addr) {
    asm volatile("ldmatrix.sync.aligned.m8n8.x4.shared.b16 {%0,%1,%2,%3}, [%4];"
        : "=r"(a[0]), "=r"(a[1]), "=r"(a[2]), "=r"(a[3]) : "r"(addr));
}
__device__ __forceinline__ void ldm_x2(uint32_t* b, uint32_t addr) {
    asm volatile("ldmatrix.sync.aligned.m8n8.x2.shared.b16 {%0,%1}, [%2];"
        : "=r"(b[0]), "=r"(b[1]) : "r"(addr));
}
__device__ __forceinline__ void ldm_x2t(uint32_t* b, uint32_t addr) {
    asm volatile("ldmatrix.sync.aligned.m8n8.x2.trans.shared.b16 {%0,%1}, [%2];"
        : "=r"(b[0]), "=r"(b[1]) : "r"(addr));
}
__device__ __forceinline__ void mma16816(float* c, const uint32_t* a, const uint32_t* b) {
    asm volatile("mma.sync.aligned.m16n8k16.row.col.f32.f16.f16.f32 "
        "{%0,%1,%2,%3},{%4,%5,%6,%7},{%8,%9},{%0,%1,%2,%3};"
        : "+f"(c[0]), "+f"(c[1]), "+f"(c[2]), "+f"(c[3])
        : "r"(a[0]), "r"(a[1]), "r"(a[2]), "r"(a[3]), "r"(b[0]), "r"(b[1]));
}
__device__ __forceinline__ void cpa16(uint32_t dst, const void* src) {
    asm volatile("cp.async.cg.shared.global [%0], [%1], 16;" :: "r"(dst), "l"(src));
}
#define CPA_COMMIT() asm volatile("cp.async.commit_group;" ::: "memory")
template<int N>
__device__ __forceinline__ void cpa_wait() {
    asm volatile("cp.async.wait_group %0;" :: "n"(N) : "memory");
}

// NN gemm: A [m rows][k cols], B [n rows][k cols]
template<int NK, int ARB, int BRB>
__device__ __forceinline__ void gemm_nn(uint32_t aB, int acb, uint32_t bB, int bcb,
                                        float acc[2][8][4], int lane, int m0, int n0) {
#pragma unroll
    for (int ks = 0; ks < NK; ks++) {
        uint32_t a[2][4];
#pragma unroll
        for (int mt = 0; mt < 2; mt++)
            ldm_x4(a[mt], aB + toff<ARB>(m0 + mt * 16 + (lane & 15),
                                         acb + ks * 32 + ((lane >> 4) << 4)));
#pragma unroll
        for (int nt = 0; nt < 8; nt++) {
            uint32_t b[2];
            ldm_x2(b, bB + toff<BRB>(n0 + nt * 8 + (lane & 7),
                                     bcb + ks * 32 + (((lane >> 3) & 1) << 4)));
            mma16816(acc[0][nt], a[0], b);
            mma16816(acc[1][nt], a[1], b);
        }
    }
}
// NT gemm: B stored [k rows][n cols]
template<int NK, int ARB, int BRB>
__device__ __forceinline__ void gemm_nt(uint32_t aB, int acb, uint32_t bB,
                                        float acc[2][8][4], int lane, int m0, int n0) {
#pragma unroll
    for (int ks = 0; ks < NK; ks++) {
        uint32_t a[2][4];
#pragma unroll
        for (int mt = 0; mt < 2; mt++)
            ldm_x4(a[mt], aB + toff<ARB>(m0 + mt * 16 + (lane & 15),
                                         acb + ks * 32 + ((lane >> 4) << 4)));
#pragma unroll
        for (int nt = 0; nt < 8; nt++) {
            uint32_t b[2];
            ldm_x2t(b, bB + toff<BRB>(ks * 16 + (lane & 15), (n0 + nt * 8) * 2));
            mma16816(acc[0][nt], a[0], b);
            mma16816(acc[1][nt], a[1], b);
        }
    }
}
__device__ __forceinline__ uint32_t packh2(float a, float b) {
    __half2 h = __floats2half2_rn(a, b);
    return *reinterpret_cast<uint32_t*>(&h);
}
__device__ __forceinline__ float fast_exp(float x) {
    float y = x * 1.4426950408889634f;
    float z = y + 12582912.0f;
    int   n = __float_as_int(z) - 0x4B400000;
    float f = y - (z - 12582912.0f);
    float p = fmaf(f, 1.5403530e-4f, 1.3333558e-3f);
    p = fmaf(f, p, 9.6181291e-3f);
    p = fmaf(f, p, 5.5504109e-2f);
    p = fmaf(f, p, 2.4022651e-1f);
    p = fmaf(f, p, 6.9314718e-1f);
    p = fmaf(f, p, 1.0f);
    return __int_as_float(__float_as_int(p) + (n << 23));
}
// cp.async 128x128 half tile (32KB, RB=256)
__device__ __forceinline__ void stage128(uint32_t dst, const __half* g, int ld, int t) {
#pragma unroll
    for (int it = 0; it < 8; it++) {
        int idx = t + it * 256, r = idx >> 4, c8 = idx & 15;
        cpa16(dst + toff<256>(r, c8 * 16), g + (size_t)r * ld + c8 * 8);
    }
}
// fp32 128x64 chunk -> fp16 tile (RB=128)
__device__ __forceinline__ void cvt64h(const float* __restrict__ g, int ld, char* s, int t) {
#pragma unroll
    for (int it = 0; it < 4; it++) {
        int idx = t + it * 256, r = idx >> 3, c8 = idx & 7;
        const float* p = g + (size_t)r * ld + c8 * 8;
        float x[8];
        *(float4*)x = *(const float4*)p;
        *(float4*)(x + 4) = *(const float4*)(p + 4);
        uint32_t h[4];
#pragma unroll
        for (int j = 0; j < 4; j++) h[j] = packh2(x[j * 2], x[j * 2 + 1]);
        *(uint4*)(s + toff<128>(r, c8 * 16)) = *(uint4*)h;
    }
}

// ---------------- prep: Wo fp32 -> fp16 rows ----------------
__global__ void __launch_bounds__(256) prep_wo_kernel(const float* __restrict__ Wo) {
    int idx = blockIdx.x * 256 + threadIdx.x;
    int r = idx >> 7, c8 = idx & 127;
    const float* p = Wo + (size_t)r * E + c8 * 8;
    float x[8];
    *(float4*)x = *(const float4*)p;
    *(float4*)(x + 4) = *(const float4*)(p + 4);
    uint32_t h[4];
#pragma unroll
    for (int j = 0; j < 4; j++) h[j] = packh2(x[j * 2], x[j * 2 + 1]);
    *(uint4*)(g_wo + (size_t)r * E + c8 * 8) = *(uint4*)h;
}

// ---------------- proj (merged q/k/v): single-pass fp16 ----------------
__global__ void __launch_bounds__(256, 2)
proj_kernel(const float* __restrict__ xq, const float* __restrict__ xk, const float* __restrict__ xv,
            const float* __restrict__ Wq, const float* __restrict__ Wk, const float* __restrict__ Wv) {
    extern __shared__ char sm[];
    uint32_t sb = smem_u32(sm);
    const int t = threadIdx.x, lane = t & 31, wid = t >> 5;
    const int w = blockIdx.x, h = blockIdx.y, z = blockIdx.z;
    const int tz = z / Bb, b = z % Bb;
    const float* x  = (tz == 0) ? xq : (tz == 1) ? xk : xv;
    const float* Wt = (tz == 0) ? Wq : (tz == 1) ? Wk : Wv;
    __half* o = (tz == 0) ? g_q : (tz == 1) ? g_k : g_v;
    const float scale = (tz == 0) ? SCALE : 1.0f;

    const int m0 = (wid & 3) * 32, n0 = (wid >> 2) * 64;
    float acc[2][8][4] = {};

    const float* xb = x + ((size_t)(b * S + w * 128)) * E + h * D;
    for (int dc = 0; dc < 2; dc++) {
        __syncthreads();
        cvt64h(xb + dc * 64, E, sm, t);
        cvt64h(Wt + dc * 64, D, sm + 16384, t);
        __syncthreads();
        gemm_nn<4, 128, 128>(sb, 0, sb + 16384, 0, acc, lane, m0, n0);
    }

    size_t base = ((size_t)(b * H + h) * S + w * 128);
#pragma unroll
    for (int mt = 0; mt < 2; mt++)
#pragma unroll
        for (int hf = 0; hf < 2; hf++) {
            int r = m0 + mt * 16 + (lane >> 2) + hf * 8;
            size_t row = (base + r) * D;
#pragma unroll
            for (int nt = 0; nt < 8; nt++) {
                int c = n0 + nt * 8 + (lane & 3) * 2;
                *(uint32_t*)(o + row + c) =
                    packh2(acc[mt][nt][hf * 2] * scale, acc[mt][nt][hf * 2 + 1] * scale);
            }
        }
}

// ---------------- attention: single-pass fp16 QK and PV, 3-buffer ring ----------------
// smem: Q 0 | P 32K | buf0 64K | buf1 96K | buf2 128K | Lacc 160K
__global__ void __launch_bounds__(256)
attn_kernel() {
    extern __shared__ char sm[];
    uint32_t sb = smem_u32(sm);
    float* Lacc = (float*)(sm + 163840);
    const int t = threadIdx.x, lane = t & 31, wid = t >> 5;
    const int w = blockIdx.x, h = blockIdx.y, b = blockIdx.z;
    const size_t base = (size_t)((b * H + h) * S);
    const int m0 = (wid & 3) * 32, n0 = (wid >> 2) * 64;

    const int j0 = (w > 0) ? w - 1 : 0;
    const int j1 = (w < NW - 1) ? w + 1 : NW - 1;
    const int nstep = (j1 - j0 + 1) * 2;   // per window: k stage, v stage

    auto buf = [&](int i) { return sb + 65536 + (uint32_t)(i % 3) * 32768; };
    auto issue_stage = [&](int ts) {
        if (ts >= nstep) return;
        int j = j0 + (ts >> 1);
        size_t roff = (base + (size_t)j * 128) * D;
        stage128(buf(ts), (ts & 1) ? g_v + roff : g_k + roff, D, t);
    };

    if (t < 128) Lacc[t] = 0.0f;
    stage128(sb, g_q + (base + (size_t)w * 128) * D, D, t);
    issue_stage(0);
    CPA_COMMIT();
    issue_stage(1);
    CPA_COMMIT();

    float oacc[2][8][4] = {};

    for (int ts = 0; ts < nstep; ts++) {
        cpa_wait<1>();
        __syncthreads();
        issue_stage(ts + 2);
        CPA_COMMIT();
        const uint32_t bf = buf(ts);
        if ((ts & 1) == 0) {   // S = q k^T, exp -> P
            float sacc[2][8][4] = {};
            gemm_nn<8, 256, 256>(sb, 0, bf, 0, sacc, lane, m0, n0);
#pragma unroll
            for (int mt = 0; mt < 2; mt++)
#pragma unroll
                for (int hf = 0; hf < 2; hf++) {
                    int r = m0 + mt * 16 + (lane >> 2) + hf * 8;
                    float rsum = 0.0f;
#pragma unroll
                    for (int nt = 0; nt < 8; nt++) {
                        float e0 = fast_exp(sacc[mt][nt][hf * 2]);
                        float e1 = fast_exp(sacc[mt][nt][hf * 2 + 1]);
                        rsum += e0 + e1;
                        int c = n0 + nt * 8 + (lane & 3) * 2;
                        *(uint32_t*)(sm + 32768 + toff<256>(r, c * 2)) = packh2(e0, e1);
                    }
                    rsum += __shfl_xor_sync(0xffffffffu, rsum, 1);
                    rsum += __shfl_xor_sync(0xffffffffu, rsum, 2);
                    if ((lane & 3) == 0) atomicAdd(&Lacc[r], rsum);
                }
        } else {               // O += P V
            gemm_nt<8, 256, 256>(sb + 32768, 0, bf, oacc, lane, m0, n0);
        }
    }
    __syncthreads();

#pragma unroll
    for (int mt = 0; mt < 2; mt++)
#pragma unroll
        for (int hf = 0; hf < 2; hf++) {
            int r = m0 + mt * 16 + (lane >> 2) + hf * 8;
            float inv = 1.0f / Lacc[r];
            size_t row = ((size_t)b * S + w * 128 + r) * E + h * D;
#pragma unroll
            for (int nt = 0; nt < 8; nt++) {
                int c = n0 + nt * 8 + (lane & 3) * 2;
                *(uint32_t*)(g_a + row + c) =
                    packh2(oacc[mt][nt][hf * 2] * inv, oacc[mt][nt][hf * 2 + 1] * inv);
            }
        }
}

// ---------------- fc: y = att @ Wo^T + bo; K=64 stages, 3-ring ----------------
// smem: 3 stages x 32KB; stage = [A 128x64 fp16 16K | W 128x64 fp16 16K]
__global__ void __launch_bounds__(256, 2)
fc_kernel(const float* __restrict__ bo, float* __restrict__ y) {
    extern __shared__ char sm[];
    uint32_t sb = smem_u32(sm);
    const int t = threadIdx.x, lane = t & 31, wid = t >> 5;
    const int nb = blockIdx.x, mb = blockIdx.y;
    const int m0 = (wid & 3) * 32, n0 = (wid >> 2) * 64;

    auto buf = [&](int i) { return sb + (uint32_t)(i % 3) * 32768; };
    auto issue_stage = [&](int s) {
        if (s >= 16) return;
        uint32_t bs = buf(s);
#pragma unroll
        for (int it = 0; it < 4; it++) {
            int idx = t + it * 256, r = idx >> 3, c8 = idx & 7;
            uint32_t o = toff<128>(r, c8 * 16);
            cpa16(bs + o,         g_a  + (size_t)(mb * 128 + r) * E + s * 64 + c8 * 8);
            cpa16(bs + 16384 + o, g_wo + (size_t)(nb * 128 + r) * E + s * 64 + c8 * 8);
        }
    };

    issue_stage(0); CPA_COMMIT();
    issue_stage(1); CPA_COMMIT();

    float acc[2][8][4] = {};
    for (int s = 0; s < 16; s++) {
        cpa_wait<1>();
        __syncthreads();
        issue_stage(s + 2);
        CPA_COMMIT();
        const uint32_t bs = buf(s);
        gemm_nn<4, 128, 128>(bs, 0, bs + 16384, 0, acc, lane, m0, n0);
    }

#pragma unroll
    for (int mt = 0; mt < 2; mt++)
#pragma unroll
        for (int hf = 0; hf < 2; hf++) {
            int r = m0 + mt * 16 + (lane >> 2) + hf * 8;
            size_t row = ((size_t)(mb * 128 + r)) * E + nb * 128;
#pragma unroll
            for (int nt = 0; nt < 8; nt++) {
                int c = n0 + nt * 8 + (lane & 3) * 2;
                float2 o;
                o.x = acc[mt][nt][hf * 2]     + bo[nb * 128 + c];
                o.y = acc[mt][nt][hf * 2 + 1] + bo[nb * 128 + c + 1];
                *(float2*)(y + row + c) = o;
            }
        }
}

// ---------------- launcher ----------------
extern "C" void kernel_launch(void* const* d_in, const int* in_sizes, int n_in,
                              void* d_out, int out_size) {
    const float* values = (const float*)d_in[0];
    const float* keys   = (const float*)d_in[1];
    const float* query  = (const float*)d_in[2];
    const float* Wv     = (const float*)d_in[3];
    const float* Wk     = (const float*)d_in[4];
    const float* Wq     = (const float*)d_in[5];
    const float* Wo     = (const float*)d_in[6];
    const float* bo     = (const float*)d_in[7];
    float* out = (float*)d_out;

    const int proj_smem = 32768;
    const int attn_smem = 163840 + 512;
    const int fc_smem   = 98304;
    cudaFuncSetAttribute(proj_kernel, cudaFuncAttributeMaxDynamicSharedMemorySize, proj_smem);
    cudaFuncSetAttribute(attn_kernel, cudaFuncAttributeMaxDynamicSharedMemorySize, attn_smem);
    cudaFuncSetAttribute(fc_kernel,   cudaFuncAttributeMaxDynamicSharedMemorySize, fc_smem);

    prep_wo_kernel<<<512, 256>>>(Wo);

    proj_kernel<<<dim3(NW, H, 3 * Bb), 256, proj_smem>>>(query, keys, values, Wq, Wk, Wv);

    attn_kernel<<<dim3(NW, H, Bb), 256, attn_smem>>>();

    fc_kernel<<<dim3(E / 128, (Bb * S) / 128), 256, fc_smem>>>(bo, out);
}

// round 12
// speedup vs baseline: 2.2016x; 1.0152x over previous
#include <cuda_runtime.h>
#include <cuda_fp16.h>
#include <cstdint>

namespace {
constexpr int Bb = 8, S = 4096, E = 1024, H = 8, D = 128, NW = 32;
constexpr float SCALE = 0.08838834764831845f;  // D^-0.5
}

__device__ __align__(128) __half g_q[(size_t)Bb*H*S*D];
__device__ __align__(128) __half g_k[(size_t)Bb*H*S*D];
__device__ __align__(128) __half g_v[(size_t)Bb*H*S*D];
__device__ __align__(128) __half g_a[(size_t)Bb*S*E];
__device__ __align__(128) __half g_wo[(size_t)E*E];

// ---------------- low-level helpers ----------------
__device__ __forceinline__ uint32_t smem_u32(const void* p) {
    uint32_t a;
    asm("{ .reg .u64 t; cvta.to.shared.u64 t, %1; cvt.u32.u64 %0, t; }" : "=r"(a) : "l"(p));
    return a;
}
template<int RB>
__device__ __forceinline__ uint32_t toff(int r, int cb) {
    return (uint32_t)(r * RB + ((((cb >> 4) ^ (r & 7)) & (RB / 16 - 1)) << 4) + (cb & 15));
}
__device__ __forceinline__ void ldm_x4(uint32_t* a, uint32_t addr) {
    asm volatile("ldmatrix.sync.aligned.m8n8.x4.shared.b16 {%0,%1,%2,%3}, [%4];"
        : "=r"(a[0]), "=r"(a[1]), "=r"(a[2]), "=r"(a[3]) : "r"(addr));
}
__device__ __forceinline__ void ldm_x2(uint32_t* b, uint32_t addr) {
    asm volatile("ldmatrix.sync.aligned.m8n8.x2.shared.b16 {%0,%1}, [%2];"
        : "=r"(b[0]), "=r"(b[1]) : "r"(addr));
}
__device__ __forceinline__ void ldm_x2t(uint32_t* b, uint32_t addr) {
    asm volatile("ldmatrix.sync.aligned.m8n8.x2.trans.shared.b16 {%0,%1}, [%2];"
        : "=r"(b[0]), "=r"(b[1]) : "r"(addr));
}
__device__ __forceinline__ void mma16816(float* c, const uint32_t* a, const uint32_t* b) {
    asm volatile("mma.sync.aligned.m16n8k16.row.col.f32.f16.f16.f32 "
        "{%0,%1,%2,%3},{%4,%5,%6,%7},{%8,%9},{%0,%1,%2,%3};"
        : "+f"(c[0]), "+f"(c[1]), "+f"(c[2]), "+f"(c[3])
        : "r"(a[0]), "r"(a[1]), "r"(a[2]), "r"(a[3]), "r"(b[0]), "r"(b[1]));
}
__device__ __forceinline__ void cpa16(uint32_t dst, const void* src) {
    asm volatile("cp.async.cg.shared.global [%0], [%1], 16;" :: "r"(dst), "l"(src));
}
#define CPA_COMMIT() asm volatile("cp.async.commit_group;" ::: "memory")
template<int N>
__device__ __forceinline__ void cpa_wait() {
    asm volatile("cp.async.wait_group %0;" :: "n"(N) : "memory");
}

// NN gemm, warp tile 32x64 (proj/attn)
template<int NK, int ARB, int BRB>
__device__ __forceinline__ void gemm_nn(uint32_t aB, int acb, uint32_t bB, int bcb,
                                        float acc[2][8][4], int lane, int m0, int n0) {
#pragma unroll
    for (int ks = 0; ks < NK; ks++) {
        uint32_t a[2][4];
#pragma unroll
        for (int mt = 0; mt < 2; mt++)
            ldm_x4(a[mt], aB + toff<ARB>(m0 + mt * 16 + (lane & 15),
                                         acb + ks * 32 + ((lane >> 4) << 4)));
#pragma unroll
        for (int nt = 0; nt < 8; nt++) {
            uint32_t b[2];
            ldm_x2(b, bB + toff<BRB>(n0 + nt * 8 + (lane & 7),
                                     bcb + ks * 32 + (((lane >> 3) & 1) << 4)));
            mma16816(acc[0][nt], a[0], b);
            mma16816(acc[1][nt], a[1], b);
        }
    }
}
// NN gemm, warp tile 64x64 (fc)
template<int NK, int ARB, int BRB>
__device__ __forceinline__ void gemm_nn64(uint32_t aB, int acb, uint32_t bB, int bcb,
                                          float acc[4][8][4], int lane, int m0, int n0) {
#pragma unroll
    for (int ks = 0; ks < NK; ks++) {
        uint32_t a[4][4];
#pragma unroll
        for (int mt = 0; mt < 4; mt++)
            ldm_x4(a[mt], aB + toff<ARB>(m0 + mt * 16 + (lane & 15),
                                         acb + ks * 32 + ((lane >> 4) << 4)));
#pragma unroll
        for (int nt = 0; nt < 8; nt++) {
            uint32_t b[2];
            ldm_x2(b, bB + toff<BRB>(n0 + nt * 8 + (lane & 7),
                                     bcb + ks * 32 + (((lane >> 3) & 1) << 4)));
#pragma unroll
            for (int mt = 0; mt < 4; mt++)
                mma16816(acc[mt][nt], a[mt], b);
        }
    }
}
// NT gemm (attn PV)
template<int NK, int ARB, int BRB>
__device__ __forceinline__ void gemm_nt(uint32_t aB, int acb, uint32_t bB,
                                        float acc[2][8][4], int lane, int m0, int n0) {
#pragma unroll
    for (int ks = 0; ks < NK; ks++) {
        uint32_t a[2][4];
#pragma unroll
        for (int mt = 0; mt < 2; mt++)
            ldm_x4(a[mt], aB + toff<ARB>(m0 + mt * 16 + (lane & 15),
                                         acb + ks * 32 + ((lane >> 4) << 4)));
#pragma unroll
        for (int nt = 0; nt < 8; nt++) {
            uint32_t b[2];
            ldm_x2t(b, bB + toff<BRB>(ks * 16 + (lane & 15), (n0 + nt * 8) * 2));
            mma16816(acc[0][nt], a[0], b);
            mma16816(acc[1][nt], a[1], b);
        }
    }
}
__device__ __forceinline__ uint32_t packh2(float a, float b) {
    __half2 h = __floats2half2_rn(a, b);
    return *reinterpret_cast<uint32_t*>(&h);
}
__device__ __forceinline__ float fast_exp(float x) {
    float y = x * 1.4426950408889634f;
    float z = y + 12582912.0f;
    int   n = __float_as_int(z) - 0x4B400000;
    float f = y - (z - 12582912.0f);
    float p = fmaf(f, 1.5403530e-4f, 1.3333558e-3f);
    p = fmaf(f, p, 9.6181291e-3f);
    p = fmaf(f, p, 5.5504109e-2f);
    p = fmaf(f, p, 2.4022651e-1f);
    p = fmaf(f, p, 6.9314718e-1f);
    p = fmaf(f, p, 1.0f);
    return __int_as_float(__float_as_int(p) + (n << 23));
}
__device__ __forceinline__ void stage128(uint32_t dst, const __half* g, int ld, int t) {
#pragma unroll
    for (int it = 0; it < 8; it++) {
        int idx = t + it * 256, r = idx >> 4, c8 = idx & 15;
        cpa16(dst + toff<256>(r, c8 * 16), g + (size_t)r * ld + c8 * 8);
    }
}
__device__ __forceinline__ void cvt64h(const float* __restrict__ g, int ld, char* s, int t) {
#pragma unroll
    for (int it = 0; it < 4; it++) {
        int idx = t + it * 256, r = idx >> 3, c8 = idx & 7;
        const float* p = g + (size_t)r * ld + c8 * 8;
        float x[8];
        *(float4*)x = *(const float4*)p;
        *(float4*)(x + 4) = *(const float4*)(p + 4);
        uint32_t h[4];
#pragma unroll
        for (int j = 0; j < 4; j++) h[j] = packh2(x[j * 2], x[j * 2 + 1]);
        *(uint4*)(s + toff<128>(r, c8 * 16)) = *(uint4*)h;
    }
}

// ---------------- prep ----------------
__global__ void __launch_bounds__(256) prep_wo_kernel(const float* __restrict__ Wo) {
    int idx = blockIdx.x * 256 + threadIdx.x;
    int r = idx >> 7, c8 = idx & 127;
    const float* p = Wo + (size_t)r * E + c8 * 8;
    float x[8];
    *(float4*)x = *(const float4*)p;
    *(float4*)(x + 4) = *(const float4*)(p + 4);
    uint32_t h[4];
#pragma unroll
    for (int j = 0; j < 4; j++) h[j] = packh2(x[j * 2], x[j * 2 + 1]);
    *(uint4*)(g_wo + (size_t)r * E + c8 * 8) = *(uint4*)h;
}

// ---------------- proj (merged q/k/v): single-pass fp16 ----------------
__global__ void __launch_bounds__(256, 2)
proj_kernel(const float* __restrict__ xq, const float* __restrict__ xk, const float* __restrict__ xv,
            const float* __restrict__ Wq, const float* __restrict__ Wk, const float* __restrict__ Wv) {
    extern __shared__ char sm[];
    uint32_t sb = smem_u32(sm);
    const int t = threadIdx.x, lane = t & 31, wid = t >> 5;
    const int w = blockIdx.x, h = blockIdx.y, z = blockIdx.z;
    const int tz = z / Bb, b = z % Bb;
    const float* x  = (tz == 0) ? xq : (tz == 1) ? xk : xv;
    const float* Wt = (tz == 0) ? Wq : (tz == 1) ? Wk : Wv;
    __half* o = (tz == 0) ? g_q : (tz == 1) ? g_k : g_v;
    const float scale = (tz == 0) ? SCALE : 1.0f;

    const int m0 = (wid & 3) * 32, n0 = (wid >> 2) * 64;
    float acc[2][8][4] = {};

    const float* xb = x + ((size_t)(b * S + w * 128)) * E + h * D;
    for (int dc = 0; dc < 2; dc++) {
        __syncthreads();
        cvt64h(xb + dc * 64, E, sm, t);
        cvt64h(Wt + dc * 64, D, sm + 16384, t);
        __syncthreads();
        gemm_nn<4, 128, 128>(sb, 0, sb + 16384, 0, acc, lane, m0, n0);
    }

    size_t base = ((size_t)(b * H + h) * S + w * 128);
#pragma unroll
    for (int mt = 0; mt < 2; mt++)
#pragma unroll
        for (int hf = 0; hf < 2; hf++) {
            int r = m0 + mt * 16 + (lane >> 2) + hf * 8;
            size_t row = (base + r) * D;
#pragma unroll
            for (int nt = 0; nt < 8; nt++) {
                int c = n0 + nt * 8 + (lane & 3) * 2;
                *(uint32_t*)(o + row + c) =
                    packh2(acc[mt][nt][hf * 2] * scale, acc[mt][nt][hf * 2 + 1] * scale);
            }
        }
}

// ---------------- attention (unchanged from R11) ----------------
__global__ void __launch_bounds__(256)
attn_kernel() {
    extern __shared__ char sm[];
    uint32_t sb = smem_u32(sm);
    float* Lacc = (float*)(sm + 163840);
    const int t = threadIdx.x, lane = t & 31, wid = t >> 5;
    const int w = blockIdx.x, h = blockIdx.y, b = blockIdx.z;
    const size_t base = (size_t)((b * H + h) * S);
    const int m0 = (wid & 3) * 32, n0 = (wid >> 2) * 64;

    const int j0 = (w > 0) ? w - 1 : 0;
    const int j1 = (w < NW - 1) ? w + 1 : NW - 1;
    const int nstep = (j1 - j0 + 1) * 2;

    auto buf = [&](int i) { return sb + 65536 + (uint32_t)(i % 3) * 32768; };
    auto issue_stage = [&](int ts) {
        if (ts >= nstep) return;
        int j = j0 + (ts >> 1);
        size_t roff = (base + (size_t)j * 128) * D;
        stage128(buf(ts), (ts & 1) ? g_v + roff : g_k + roff, D, t);
    };

    if (t < 128) Lacc[t] = 0.0f;
    stage128(sb, g_q + (base + (size_t)w * 128) * D, D, t);
    issue_stage(0);
    CPA_COMMIT();
    issue_stage(1);
    CPA_COMMIT();

    float oacc[2][8][4] = {};

    for (int ts = 0; ts < nstep; ts++) {
        cpa_wait<1>();
        __syncthreads();
        issue_stage(ts + 2);
        CPA_COMMIT();
        const uint32_t bf = buf(ts);
        if ((ts & 1) == 0) {
            float sacc[2][8][4] = {};
            gemm_nn<8, 256, 256>(sb, 0, bf, 0, sacc, lane, m0, n0);
#pragma unroll
            for (int mt = 0; mt < 2; mt++)
#pragma unroll
                for (int hf = 0; hf < 2; hf++) {
                    int r = m0 + mt * 16 + (lane >> 2) + hf * 8;
                    float rsum = 0.0f;
#pragma unroll
                    for (int nt = 0; nt < 8; nt++) {
                        float e0 = fast_exp(sacc[mt][nt][hf * 2]);
                        float e1 = fast_exp(sacc[mt][nt][hf * 2 + 1]);
                        rsum += e0 + e1;
                        int c = n0 + nt * 8 + (lane & 3) * 2;
                        *(uint32_t*)(sm + 32768 + toff<256>(r, c * 2)) = packh2(e0, e1);
                    }
                    rsum += __shfl_xor_sync(0xffffffffu, rsum, 1);
                    rsum += __shfl_xor_sync(0xffffffffu, rsum, 2);
                    if ((lane & 3) == 0) atomicAdd(&Lacc[r], rsum);
                }
        } else {
            gemm_nt<8, 256, 256>(sb + 32768, 0, bf, oacc, lane, m0, n0);
        }
    }
    __syncthreads();

#pragma unroll
    for (int mt = 0; mt < 2; mt++)
#pragma unroll
        for (int hf = 0; hf < 2; hf++) {
            int r = m0 + mt * 16 + (lane >> 2) + hf * 8;
            float inv = 1.0f / Lacc[r];
            size_t row = ((size_t)b * S + w * 128 + r) * E + h * D;
#pragma unroll
            for (int nt = 0; nt < 8; nt++) {
                int c = n0 + nt * 8 + (lane & 3) * 2;
                *(uint32_t*)(g_a + row + c) =
                    packh2(oacc[mt][nt][hf * 2] * inv, oacc[mt][nt][hf * 2 + 1] * inv);
            }
        }
}

// ---------------- fc: 128 threads, 4 warps of 64x64, K=64 3-ring ----------------
// smem: 3 stages x 32KB; stage = [A 128x64 16K | W 128x64 16K], RB=128
__global__ void __launch_bounds__(128)
fc_kernel(const float* __restrict__ bo, float* __restrict__ y) {
    extern __shared__ char sm[];
    uint32_t sb = smem_u32(sm);
    const int t = threadIdx.x, lane = t & 31, wid = t >> 5;
    const int nb = blockIdx.x, mb = blockIdx.y;
    const int m0 = (wid & 1) * 64, n0 = (wid >> 1) * 64;

    auto buf = [&](int i) { return sb + (uint32_t)(i % 3) * 32768; };
    auto issue_stage = [&](int s) {
        if (s >= 16) return;
        uint32_t bs = buf(s);
#pragma unroll
        for (int it = 0; it < 8; it++) {
            int idx = t + it * 128, r = idx >> 3, c8 = idx & 7;
            uint32_t o = toff<128>(r, c8 * 16);
            cpa16(bs + o,         g_a  + (size_t)(mb * 128 + r) * E + s * 64 + c8 * 8);
            cpa16(bs + 16384 + o, g_wo + (size_t)(nb * 128 + r) * E + s * 64 + c8 * 8);
        }
    };

    issue_stage(0); CPA_COMMIT();
    issue_stage(1); CPA_COMMIT();

    float acc[4][8][4] = {};
    for (int s = 0; s < 16; s++) {
        cpa_wait<1>();
        __syncthreads();
        issue_stage(s + 2);
        CPA_COMMIT();
        const uint32_t bs = buf(s);
        gemm_nn64<4, 128, 128>(bs, 0, bs + 16384, 0, acc, lane, m0, n0);
    }

#pragma unroll
    for (int mt = 0; mt < 4; mt++)
#pragma unroll
        for (int hf = 0; hf < 2; hf++) {
            int r = m0 + mt * 16 + (lane >> 2) + hf * 8;
            size_t row = ((size_t)(mb * 128 + r)) * E + nb * 128;
#pragma unroll
            for (int nt = 0; nt < 8; nt++) {
                int c = n0 + nt * 8 + (lane & 3) * 2;
                float2 o;
                o.x = acc[mt][nt][hf * 2]     + bo[nb * 128 + c];
                o.y = acc[mt][nt][hf * 2 + 1] + bo[nb * 128 + c + 1];
                *(float2*)(y + row + c) = o;
            }
        }
}

// ---------------- launcher ----------------
extern "C" void kernel_launch(void* const* d_in, const int* in_sizes, int n_in,
                              void* d_out, int out_size) {
    const float* values = (const float*)d_in[0];
    const float* keys   = (const float*)d_in[1];
    const float* query  = (const float*)d_in[2];
    const float* Wv     = (const float*)d_in[3];
    const float* Wk     = (const float*)d_in[4];
    const float* Wq     = (const float*)d_in[5];
    const float* Wo     = (const float*)d_in[6];
    const float* bo     = (const float*)d_in[7];
    float* out = (float*)d_out;

    const int proj_smem = 32768;
    const int attn_smem = 163840 + 512;
    const int fc_smem   = 98304;
    cudaFuncSetAttribute(proj_kernel, cudaFuncAttributeMaxDynamicSharedMemorySize, proj_smem);
    cudaFuncSetAttribute(attn_kernel, cudaFuncAttributeMaxDynamicSharedMemorySize, attn_smem);
    cudaFuncSetAttribute(fc_kernel,   cudaFuncAttributeMaxDynamicSharedMemorySize, fc_smem);

    prep_wo_kernel<<<512, 256>>>(Wo);

    proj_kernel<<<dim3(NW, H, 3 * Bb), 256, proj_smem>>>(query, keys, values, Wq, Wk, Wv);

    attn_kernel<<<dim3(NW, H, Bb), 256, attn_smem>>>();

    fc_kernel<<<dim3(E / 128, (Bb * S) / 128), 128, fc_smem>>>(bo, out);
}